// round 5
// baseline (speedup 1.0000x reference)
#include <cuda_runtime.h>

#define CH     512
#define HW     4096        // 64*64
#define NPIX   32768       // 8 * 4096
#define NCHUNK 32          // channel chunks of 16
#define CHPC   16          // channels per chunk
#define NITEMS 4096        // 128 px-tiles * 32 chunks
#define GRID_DOT 592       // 148 SMs * 4 blocks, exactly one wave

// Static device scratch (no dynamic allocation allowed).
__device__ __align__(16) float g_p1[NCHUNK][NPIX];
__device__ __align__(16) float g_p2[NCHUNK][NPIX];
__device__ float g_recon[NPIX];
__device__ float g_ref[NPIX];

// ---- packed f32x2 helpers (Blackwell FFMA2 path, PTX-only) -----------------
typedef unsigned long long ull;
__device__ __forceinline__ ull pk2(float lo, float hi) {
    ull r; asm("mov.b64 %0, {%1, %2};" : "=l"(r) : "f"(lo), "f"(hi)); return r;
}
__device__ __forceinline__ void unpk2(ull v, float& lo, float& hi) {
    asm("mov.b64 {%0, %1}, %2;" : "=f"(lo), "=f"(hi) : "l"(v));
}
__device__ __forceinline__ ull fma2(ull a, ull b, ull c) {
    ull d; asm("fma.rn.f32x2 %0, %1, %2, %3;" : "=l"(d) : "l"(a), "l"(b), "l"(c));
    return d;
}
__device__ __forceinline__ ull mul2(ull a, ull b) {
    ull d; asm("mul.rn.f32x2 %0, %1, %2;" : "=l"(d) : "l"(a), "l"(b)); return d;
}

// ---------------------------------------------------------------------------
// Kernel A: partial channel dot-products, persistent grid-stride form.
// grid 592 = 148*4 resident blocks (launch_bounds enforces 4/SM). 4096 items
// of (256-px tile, 16-ch chunk) -> 6-7 items/block, <=1.2% imbalance.
// Scalar coalesced loads (128B/warp); weights preloaded to SMEM as float2.
// ---------------------------------------------------------------------------
__global__ void __launch_bounds__(256, 4) k_dot(
        const float* __restrict__ spade, const float* __restrict__ x,
        const float* __restrict__ w1, const float* __restrict__ w2) {
    __shared__ float2 ws[CH];
    const int t = threadIdx.x;
    for (int c = t; c < CH; c += 256) ws[c] = make_float2(w1[c], w2[c]);
    __syncthreads();

    for (int e = blockIdx.x; e < NITEMS; e += GRID_DOT) {
        const int tile  = e & 127;          // 128 tiles of 256 px
        const int chunk = e >> 7;           // 32 chunks of 16 ch
        const int P  = tile * 256 + t;
        const int b  = P >> 12;
        const int hw = P & (HW - 1);
        const size_t base = (size_t)b * CH * HW + (size_t)chunk * CHPC * HW + hw;
        const float* fp = spade + base;
        const float* xp = x + base;
        const float2* wp = ws + chunk * CHPC;

        float s1 = 0.f, s2 = 0.f;
        #pragma unroll
        for (int c = 0; c < CHPC; c++) {
            const float f = __ldcs(fp + (size_t)c * HW);
            const float v = __ldcs(xp + (size_t)c * HW);
            const float2 w = wp[c];
            s1 += f * w.x;
            s2 += v * w.y;
        }
        g_p1[chunk][P] = s1;
        g_p2[chunk][P] = s2;
    }
}

// ---------------------------------------------------------------------------
// Kernel B: reduce 32 chunk partials + bias + ReLU -> recon / reference maps.
// ---------------------------------------------------------------------------
__global__ void __launch_bounds__(256) k_reduce(
        const float* __restrict__ b1, const float* __restrict__ b2) {
    const int P = blockIdx.x * 256 + threadIdx.x;
    float s1 = b1[0];
    float s2 = b2[0];
    #pragma unroll
    for (int k = 0; k < NCHUNK; k++) {
        s1 += g_p1[k][P];
        s2 += g_p2[k][P];
    }
    g_recon[P] = fmaxf(s1, 0.f);
    g_ref[P]   = fmaxf(s2, 0.f);
}

// ---------------------------------------------------------------------------
// Kernel C: per-patch 2x2 correlation + first-occurrence argmax + gather.
// grid 512: block = (b, group of 16 patches), 8 warps. Each warp makes ONE
// sweep over the 64 window rows and evaluates BOTH of its patches per row,
// sharing the LDS row loads (halves SMEM traffic vs sweep-per-patch).
// Single padded tile; neighbor column comes from a second LDS.64 (no shadow
// tile, no shuffle). Tie handling preserves jnp.argmax first-occurrence.
// ---------------------------------------------------------------------------
__global__ void __launch_bounds__(256) k_match(float* __restrict__ out) {
    __shared__ float Ra[65][68];   // recon tile; row 64 and cols>=64 are zero
    const int t    = threadIdx.x;
    const int b    = blockIdx.x >> 6;
    const int grp  = blockIdx.x & 63;
    const float* rb = g_recon + b * HW;

    for (int i = t; i < 65 * 68; i += 256) {
        const int row = i / 68;
        const int col = i - row * 68;
        Ra[row][col] = (row < 64 && col < 64) ? rb[row * 64 + col] : 0.f;
    }
    __syncthreads();

    const int lane = t & 31;
    const int w    = t >> 5;
    const float* refb = g_ref + b * HW;

    // two patches per warp, one shared sweep
    const int lA = grp * 16 + w * 2;
    const int lB = lA + 1;
    const int piA = lA >> 5, pjA = lA & 31;
    const int piB = lB >> 5, pjB = lB & 31;

    const float a00 = refb[(2 * piA) * 64 + 2 * pjA];
    const float a01 = refb[(2 * piA) * 64 + 2 * pjA + 1];
    const float a10 = refb[(2 * piA + 1) * 64 + 2 * pjA];
    const float a11 = refb[(2 * piA + 1) * 64 + 2 * pjA + 1];
    const float b00 = refb[(2 * piB) * 64 + 2 * pjB];
    const float b01 = refb[(2 * piB) * 64 + 2 * pjB + 1];
    const float b10 = refb[(2 * piB + 1) * 64 + 2 * pjB];
    const float b11 = refb[(2 * piB + 1) * 64 + 2 * pjB + 1];
    const ull ca00 = pk2(a00, a00), ca01 = pk2(a01, a01);
    const ull ca10 = pk2(a10, a10), ca11 = pk2(a11, a11);
    const ull cb00 = pk2(b00, b00), cb01 = pk2(b01, b01);
    const ull cb10 = pk2(b10, b10), cb11 = pk2(b11, b11);

    const int q = lane * 2;
    ull cur01 = *(const ull*)&Ra[0][q];
    {
        // seed v12 from row 0
    }
    float r0, r1; unpk2(cur01, r0, r1);
    float r2 = Ra[0][q + 2];
    ull v12 = pk2(r1, r2);

    float bvA = -1.f, bvB = -1.f;     // all y >= 0 (ReLU inputs)
    int   biA = 0,    biB = 0;

    #pragma unroll 4
    for (int p = 0; p < 64; p++) {
        const ull nxt01 = *(const ull*)&Ra[p + 1][q];
        const ull nxt23 = *(const ull*)&Ra[p + 1][q + 2];
        float n0, n1; unpk2(nxt01, n0, n1);
        float n2, nx; unpk2(nxt23, n2, nx);
        const ull w12 = pk2(n1, n2);

        const ull yA = fma2(ca11, w12, fma2(ca10, nxt01,
                       fma2(ca01, v12, mul2(ca00, cur01))));
        const ull yB = fma2(cb11, w12, fma2(cb10, nxt01,
                       fma2(cb01, v12, mul2(cb00, cur01))));

        const int idx = (p << 6) + q;
        {
            float y0, y1; unpk2(yA, y0, y1);
            const bool  g  = (y1 > y0);
            const float rv = g ? y1 : y0;
            const int   ri = idx + (g ? 1 : 0);
            if (rv > bvA) { bvA = rv; biA = ri; }
        }
        {
            float y0, y1; unpk2(yB, y0, y1);
            const bool  g  = (y1 > y0);
            const float rv = g ? y1 : y0;
            const int   ri = idx + (g ? 1 : 0);
            if (rv > bvB) { bvB = rv; biB = ri; }
        }
        cur01 = nxt01;
        v12   = w12;
    }

    // Warp argmax per patch; ties -> smallest flat index (jnp.argmax).
    #pragma unroll
    for (int off = 16; off; off >>= 1) {
        const float vA = __shfl_down_sync(0xffffffffu, bvA, off);
        const int   iA = __shfl_down_sync(0xffffffffu, biA, off);
        if (vA > bvA || (vA == bvA && iA < biA)) { bvA = vA; biA = iA; }
        const float vB = __shfl_down_sync(0xffffffffu, bvB, off);
        const int   iB = __shfl_down_sync(0xffffffffu, biB, off);
        if (vB > bvB || (vB == bvB && iB < biB)) { bvB = vB; biB = iB; }
    }

    if (lane == 0) {
        {
            const int g  = biA >> 2;          // offset // 4
            const int gi = g >> 5, gj = g & 31;
            float* o = out + b * HW + (2 * piA) * 64 + 2 * pjA;
            o[0]  = Ra[2 * gi][2 * gj];
            o[1]  = Ra[2 * gi][2 * gj + 1];
            o[64] = Ra[2 * gi + 1][2 * gj];
            o[65] = Ra[2 * gi + 1][2 * gj + 1];
        }
        {
            const int g  = biB >> 2;
            const int gi = g >> 5, gj = g & 31;
            float* o = out + b * HW + (2 * piB) * 64 + 2 * pjB;
            o[0]  = Ra[2 * gi][2 * gj];
            o[1]  = Ra[2 * gi][2 * gj + 1];
            o[64] = Ra[2 * gi + 1][2 * gj];
            o[65] = Ra[2 * gi + 1][2 * gj + 1];
        }
    }
}

extern "C" void kernel_launch(void* const* d_in, const int* in_sizes, int n_in,
                              void* d_out, int out_size) {
    const float* spade = (const float*)d_in[0];
    const float* x     = (const float*)d_in[1];
    const float* w1    = (const float*)d_in[2];
    const float* b1    = (const float*)d_in[3];
    const float* w2    = (const float*)d_in[4];
    const float* b2    = (const float*)d_in[5];
    float* out = (float*)d_out;

    k_dot<<<GRID_DOT, 256>>>(spade, x, w1, w2);
    k_reduce<<<128, 256>>>(b1, b2);
    k_match<<<512, 256>>>(out);
}

// round 6
// speedup vs baseline: 1.1328x; 1.1328x over previous
#include <cuda_runtime.h>

#define CH     512
#define HW     4096        // 64*64
#define NPIX   32768       // 8 * 4096

// Static device scratch (no dynamic allocation allowed).
__device__ float g_recon[NPIX];
__device__ float g_ref[NPIX];

// ---- packed f32x2 helpers (Blackwell FFMA2 path, PTX-only) -----------------
typedef unsigned long long ull;
__device__ __forceinline__ ull pk2(float lo, float hi) {
    ull r; asm("mov.b64 %0, {%1, %2};" : "=l"(r) : "f"(lo), "f"(hi)); return r;
}
__device__ __forceinline__ void unpk2(ull v, float& lo, float& hi) {
    asm("mov.b64 {%0, %1}, %2;" : "=f"(lo), "=f"(hi) : "l"(v));
}
__device__ __forceinline__ ull fma2(ull a, ull b, ull c) {
    ull d; asm("fma.rn.f32x2 %0, %1, %2, %3;" : "=l"(d) : "l"(a), "l"(b), "l"(c));
    return d;
}
__device__ __forceinline__ ull mul2(ull a, ull b) {
    ull d; asm("mul.rn.f32x2 %0, %1, %2;" : "=l"(d) : "l"(a), "l"(b)); return d;
}

// ---------------------------------------------------------------------------
// Kernel A (fused dot + reduce): one block = 64 consecutive pixels x ALL 512
// channels. 512 blocks = one wave (R4-proven). Thread (i = t&15 -> float4
// pixel slot, j = t>>4 -> 32-channel group) accumulates with LDG.128 (R4's
// proven coalescing/MLP profile), then a small SMEM cross-group reduction
// produces recon/ref directly. No scratch globals, no second kernel.
// ---------------------------------------------------------------------------
__global__ void __launch_bounds__(256) k_fused(
        const float* __restrict__ spade, const float* __restrict__ x,
        const float* __restrict__ w1, const float* __restrict__ w2,
        const float* __restrict__ b1, const float* __restrict__ b2) {
    __shared__ float2 ws[CH];                 // (w1, w2) pairs
    __shared__ float4 red1[16][16];           // [group][float4 slot]
    __shared__ float4 red2[16][16];
    const int t = threadIdx.x;
    for (int c = t; c < CH; c += 256) ws[c] = make_float2(w1[c], w2[c]);
    __syncthreads();

    const int pt  = blockIdx.x;               // 64-px tile index (0..511)
    const int b   = pt >> 6;                  // batch
    const int hw0 = (pt & 63) * 64;           // tile base within the image
    const int i   = t & 15;                   // float4 slot (4 px)
    const int j   = t >> 4;                   // channel group (32 ch)

    const size_t base = (size_t)b * CH * HW + (size_t)(j * 32) * HW + hw0 + i * 4;
    const float4* fp = (const float4*)(spade + base);
    const float4* xp = (const float4*)(x + base);
    const float2* wp = ws + j * 32;

    float4 a1 = make_float4(0.f, 0.f, 0.f, 0.f);
    float4 a2 = make_float4(0.f, 0.f, 0.f, 0.f);
    #pragma unroll 8
    for (int c = 0; c < 32; c++) {
        float4 f = __ldcs(fp + (size_t)c * (HW / 4));
        float4 v = __ldcs(xp + (size_t)c * (HW / 4));
        const float2 w = wp[c];
        a1.x += f.x * w.x; a1.y += f.y * w.x; a1.z += f.z * w.x; a1.w += f.w * w.x;
        a2.x += v.x * w.y; a2.y += v.y * w.y; a2.z += v.z * w.y; a2.w += v.w * w.y;
    }
    red1[j][i] = a1;
    red2[j][i] = a2;
    __syncthreads();

    // Cross-group reduction: warp0 lanes 0-15 -> recon, warp1 lanes 0-15 -> ref
    if (t < 16) {
        float4 s = make_float4(0.f, 0.f, 0.f, 0.f);
        #pragma unroll
        for (int g = 0; g < 16; g++) {
            const float4 a = red1[g][t];
            s.x += a.x; s.y += a.y; s.z += a.z; s.w += a.w;
        }
        const float bb = b1[0];
        s.x = fmaxf(s.x + bb, 0.f); s.y = fmaxf(s.y + bb, 0.f);
        s.z = fmaxf(s.z + bb, 0.f); s.w = fmaxf(s.w + bb, 0.f);
        *(float4*)&g_recon[pt * 64 + t * 4] = s;
    } else if (t >= 32 && t < 48) {
        const int i2 = t - 32;
        float4 s = make_float4(0.f, 0.f, 0.f, 0.f);
        #pragma unroll
        for (int g = 0; g < 16; g++) {
            const float4 a = red2[g][i2];
            s.x += a.x; s.y += a.y; s.z += a.z; s.w += a.w;
        }
        const float bb = b2[0];
        s.x = fmaxf(s.x + bb, 0.f); s.y = fmaxf(s.y + bb, 0.f);
        s.z = fmaxf(s.z + bb, 0.f); s.w = fmaxf(s.w + bb, 0.f);
        *(float4*)&g_ref[pt * 64 + i2 * 4] = s;
    }
}

// ---------------------------------------------------------------------------
// Kernel B: per-patch 2x2 correlation + first-occurrence argmax + gather.
// grid 512: block = (b, group of 16 patches), 8 warps. One sweep per warp
// serving both of its patches (shared LDS row loads). Single padded tile;
// right-neighbor column from a second LDS.64. jnp.argmax first-occurrence
// tie semantics preserved end-to-end.
// ---------------------------------------------------------------------------
__global__ void __launch_bounds__(256) k_match(float* __restrict__ out) {
    __shared__ float Ra[65][68];   // recon tile; row 64 and cols>=64 are zero
    const int t    = threadIdx.x;
    const int b    = blockIdx.x >> 6;
    const int grp  = blockIdx.x & 63;
    const float* rb = g_recon + b * HW;

    for (int i = t; i < 65 * 68; i += 256) {
        const int row = i / 68;
        const int col = i - row * 68;
        Ra[row][col] = (row < 64 && col < 64) ? rb[row * 64 + col] : 0.f;
    }
    __syncthreads();

    const int lane = t & 31;
    const int w    = t >> 5;
    const float* refb = g_ref + b * HW;

    // two patches per warp, one shared sweep
    const int lA = grp * 16 + w * 2;
    const int lB = lA + 1;
    const int piA = lA >> 5, pjA = lA & 31;
    const int piB = lB >> 5, pjB = lB & 31;

    const float a00 = refb[(2 * piA) * 64 + 2 * pjA];
    const float a01 = refb[(2 * piA) * 64 + 2 * pjA + 1];
    const float a10 = refb[(2 * piA + 1) * 64 + 2 * pjA];
    const float a11 = refb[(2 * piA + 1) * 64 + 2 * pjA + 1];
    const float b00 = refb[(2 * piB) * 64 + 2 * pjB];
    const float b01 = refb[(2 * piB) * 64 + 2 * pjB + 1];
    const float b10 = refb[(2 * piB + 1) * 64 + 2 * pjB];
    const float b11 = refb[(2 * piB + 1) * 64 + 2 * pjB + 1];
    const ull ca00 = pk2(a00, a00), ca01 = pk2(a01, a01);
    const ull ca10 = pk2(a10, a10), ca11 = pk2(a11, a11);
    const ull cb00 = pk2(b00, b00), cb01 = pk2(b01, b01);
    const ull cb10 = pk2(b10, b10), cb11 = pk2(b11, b11);

    const int q = lane * 2;
    ull cur01 = *(const ull*)&Ra[0][q];
    float r0, r1; unpk2(cur01, r0, r1);
    float r2 = Ra[0][q + 2];
    ull v12 = pk2(r1, r2);

    float bvA = -1.f, bvB = -1.f;     // all y >= 0 (ReLU inputs)
    int   biA = 0,    biB = 0;

    #pragma unroll 4
    for (int p = 0; p < 64; p++) {
        const ull nxt01 = *(const ull*)&Ra[p + 1][q];
        const ull nxt23 = *(const ull*)&Ra[p + 1][q + 2];
        float n0, n1; unpk2(nxt01, n0, n1);
        float n2, nx; unpk2(nxt23, n2, nx);
        const ull w12 = pk2(n1, n2);

        const ull yA = fma2(ca11, w12, fma2(ca10, nxt01,
                       fma2(ca01, v12, mul2(ca00, cur01))));
        const ull yB = fma2(cb11, w12, fma2(cb10, nxt01,
                       fma2(cb01, v12, mul2(cb00, cur01))));

        const int idx = (p << 6) + q;
        {
            float y0, y1; unpk2(yA, y0, y1);
            const bool  g  = (y1 > y0);
            const float rv = g ? y1 : y0;
            const int   ri = idx + (g ? 1 : 0);
            if (rv > bvA) { bvA = rv; biA = ri; }
        }
        {
            float y0, y1; unpk2(yB, y0, y1);
            const bool  g  = (y1 > y0);
            const float rv = g ? y1 : y0;
            const int   ri = idx + (g ? 1 : 0);
            if (rv > bvB) { bvB = rv; biB = ri; }
        }
        cur01 = nxt01;
        v12   = w12;
    }

    // Warp argmax per patch; ties -> smallest flat index (jnp.argmax).
    #pragma unroll
    for (int off = 16; off; off >>= 1) {
        const float vA = __shfl_down_sync(0xffffffffu, bvA, off);
        const int   iA = __shfl_down_sync(0xffffffffu, biA, off);
        if (vA > bvA || (vA == bvA && iA < biA)) { bvA = vA; biA = iA; }
        const float vB = __shfl_down_sync(0xffffffffu, bvB, off);
        const int   iB = __shfl_down_sync(0xffffffffu, biB, off);
        if (vB > bvB || (vB == bvB && iB < biB)) { bvB = vB; biB = iB; }
    }

    if (lane == 0) {
        {
            const int g  = biA >> 2;          // offset // 4
            const int gi = g >> 5, gj = g & 31;
            float* o = out + b * HW + (2 * piA) * 64 + 2 * pjA;
            o[0]  = Ra[2 * gi][2 * gj];
            o[1]  = Ra[2 * gi][2 * gj + 1];
            o[64] = Ra[2 * gi + 1][2 * gj];
            o[65] = Ra[2 * gi + 1][2 * gj + 1];
        }
        {
            const int g  = biB >> 2;
            const int gi = g >> 5, gj = g & 31;
            float* o = out + b * HW + (2 * piB) * 64 + 2 * pjB;
            o[0]  = Ra[2 * gi][2 * gj];
            o[1]  = Ra[2 * gi][2 * gj + 1];
            o[64] = Ra[2 * gi + 1][2 * gj];
            o[65] = Ra[2 * gi + 1][2 * gj + 1];
        }
    }
}

extern "C" void kernel_launch(void* const* d_in, const int* in_sizes, int n_in,
                              void* d_out, int out_size) {
    const float* spade = (const float*)d_in[0];
    const float* x     = (const float*)d_in[1];
    const float* w1    = (const float*)d_in[2];
    const float* b1    = (const float*)d_in[3];
    const float* w2    = (const float*)d_in[4];
    const float* b2    = (const float*)d_in[5];
    float* out = (float*)d_out;

    k_fused<<<512, 256>>>(spade, x, w1, w2, b1, b2);
    k_match<<<512, 256>>>(out);
}